// round 9
// baseline (speedup 1.0000x reference)
#include <cuda_runtime.h>
#include <cuda_bf16.h>
#include <cstdint>

// CIN (xDeepFM) fused 3-layer kernel via mma.sync (HMMA) bf16 3-term split.
// Round 8: 2 k-chunks per iteration -> barriers halved (291), one cp.async
// commit group per iteration, rigorous wait_group0+barrier before reading a
// freshly filled stage. 3-stage 8KB swizzled W ring as in round 7.

#define NT 256
#define KCH 576                 // total 16-wide k chunks: 64 + 256 + 256
#define WTERM 4096              // 128 n-rows * 32B (16 bf16), swizzled
#define CHUNK_BYTES (2 * WTERM) // 8192: hi term + lo term
#define NSTAGE 3

// smem byte offsets
#define SM_X0T   0                  // 128 rows * 36 f32 = 18432
#define SM_ST    18432              // 128 rows * 132 f32 = 67584
#define SM_W     86016              // 3 stages * 8192 = 24576
#define SM_BIAS  110592             // 384 f32 = 1536
#define SMEM_TOTAL 112128

__device__ __align__(16) unsigned char WT_buf[(size_t)KCH * CHUNK_BYTES]; // 4.7MB

// ------------- helpers -------------
__device__ __forceinline__ uint32_t smem_u32(const void* p) {
    uint32_t a;
    asm("{ .reg .u64 t; cvta.to.shared.u64 t, %1; cvt.u32.u64 %0, t; }" : "=r"(a) : "l"(p));
    return a;
}
__device__ __forceinline__ uint32_t pkbf(float lo, float hi) {
    uint32_t r;  // first asm operand -> high half
    asm("cvt.rn.bf16x2.f32 %0, %1, %2;" : "=r"(r) : "f"(hi), "f"(lo));
    return r;
}
__device__ __forceinline__ float bflo(uint32_t p) { return __uint_as_float(p << 16); }
__device__ __forceinline__ float bfhi(uint32_t p) { return __uint_as_float(p & 0xffff0000u); }

__device__ __forceinline__ void ldsm4(uint32_t a, uint32_t& r0, uint32_t& r1,
                                      uint32_t& r2, uint32_t& r3) {
    asm volatile("ldmatrix.sync.aligned.m8n8.x4.shared.b16 {%0,%1,%2,%3}, [%4];"
                 : "=r"(r0), "=r"(r1), "=r"(r2), "=r"(r3) : "r"(a));
}
__device__ __forceinline__ void mma16816(float* c, const uint32_t* a, uint32_t b0, uint32_t b1) {
    asm volatile("mma.sync.aligned.m16n8k16.row.col.f32.bf16.bf16.f32 "
                 "{%0,%1,%2,%3}, {%4,%5,%6,%7}, {%8,%9}, {%0,%1,%2,%3};"
                 : "+f"(c[0]), "+f"(c[1]), "+f"(c[2]), "+f"(c[3])
                 : "r"(a[0]), "r"(a[1]), "r"(a[2]), "r"(a[3]), "r"(b0), "r"(b1));
}
__device__ __forceinline__ void cpasync16(uint32_t dst, const void* src) {
    asm volatile("cp.async.cg.shared.global [%0], [%1], 16;" :: "r"(dst), "l"(src) : "memory");
}
#define CP_COMMIT() asm volatile("cp.async.commit_group;" ::: "memory")
#define CP_WAIT0()  asm volatile("cp.async.wait_group 0;" ::: "memory")

// swizzled byte offset of the 16B half (n-row, khalf) within one term
__device__ __host__ __forceinline__ int wsw(int n, int khalf) {
    return n * 32 + ((khalf ^ ((n >> 2) & 1)) << 4);
}

// ------------- prep: split W -> bf16 hi/lo, swizzled chunk layout == smem -------------
__global__ void prep_w(const float* __restrict__ W0, const float* __restrict__ W1,
                       const float* __restrict__ W2) {
    int i = blockIdx.x * blockDim.x + threadIdx.x;   // over 9216*128
    if (i >= 9216 * 128) return;
    int k = i >> 7, n = i & 127;
    float w;
    if (k < 1024)      w = W0[k * 128 + n];
    else if (k < 5120) w = W1[(k - 1024) * 128 + n];
    else               w = W2[(k - 5120) * 128 + n];
    __nv_bfloat16 hb = __float2bfloat16(w);
    __nv_bfloat16 lb = __float2bfloat16(w - __bfloat162float(hb));
    int c = k >> 4, kk = k & 15;
    int off = wsw(n, kk >> 3) + (kk & 7) * 2;
    unsigned char* base = WT_buf + (size_t)c * CHUNK_BYTES + off;
    *(__nv_bfloat16*)(base)         = hb;   // hi term
    *(__nv_bfloat16*)(base + WTERM) = lb;   // lo term
}

// ------------- main kernel -------------
__global__ void __launch_bounds__(NT, 2)
cin_hmma_kernel(const float* __restrict__ X,
                const float* __restrict__ B0, const float* __restrict__ B1,
                const float* __restrict__ B2, float* __restrict__ out)
{
    extern __shared__ __align__(16) char smem[];
    float* x0t  = (float*)(smem + SM_X0T);   // [row][36] (f stride)
    float* st   = (float*)(smem + SM_ST);    // [row][132] (g stride)
    float* bias = (float*)(smem + SM_BIAS);  // [384]
    const uint32_t wsm = smem_u32(smem) + SM_W;

    const int tid = threadIdx.x, wid = tid >> 5, lane = tid & 31;
    const int wm = wid >> 1, wn = wid & 1;     // warp grid 4(m=batch) x 2(n)
    const int b0g = blockIdx.x * 4;
    const int r0 = lane >> 2;                  // row-in-frag 0..7
    const int c0 = (lane & 3) * 2;             // col pair base

    // ---- prologue: cp.async chunks 0,1 as one group ----
    {
        const unsigned char* s0 = WT_buf + tid * 16;
        cpasync16(wsm + tid * 16,        s0);
        cpasync16(wsm + tid * 16 + 4096, s0 + 4096);
        const unsigned char* s1 = WT_buf + CHUNK_BYTES + tid * 16;
        cpasync16(wsm + CHUNK_BYTES + tid * 16,        s1);
        cpasync16(wsm + CHUNK_BYTES + tid * 16 + 4096, s1 + 4096);
        CP_COMMIT();
    }

    // ---- load x0 transposed + init state + bias ----
    {
        const float* Xb = X + (size_t)b0g * 1024;
        for (int i = tid; i < 4096; i += NT) {
            int b = i >> 10, f = (i >> 5) & 31, d = i & 31;
            float v = Xb[i];
            int row = b * 32 + d;
            x0t[row * 36 + f] = v;
            st[row * 132 + f] = v;     // layer-0 state = x0 (g = f)
        }
        for (int i = tid; i < 128; i += NT) {
            bias[i] = B0[i]; bias[128 + i] = B1[i]; bias[256 + i] = B2[i];
        }
    }
    CP_WAIT0();          // chunks 0,1 landed (own); barrier makes it CTA-wide
    __syncthreads();

    // per-j ldsm swizzled offsets within a term
    const int kh = (lane >> 3) & 1;
    uint32_t nroff[4];
    #pragma unroll
    for (int j = 0; j < 4; ++j) {
        const int nrow = (wn * 8 + 2 * j + ((lane >> 4) & 1)) * 8 + (lane & 7);
        nroff[j] = (uint32_t)wsw(nrow, kh);
    }

    uint32_t bh[4][4], bl[4][4];    // B fragments (reloaded per chunk)
    uint32_t ah[2][4], al[2][4];    // A fragments (rebuilt per chunk)

    int cg = 0;      // global chunk counter (even at iteration tops)

    #pragma unroll 1
    for (int l = 0; l < 3; ++l) {
        const int lg2 = (l == 0) ? 1 : 3;        // chunks per f = fk/16
        const int nchunk = (l == 0) ? 64 : 256;

        float acc[2][8][4];
        #pragma unroll
        for (int fr = 0; fr < 2; ++fr)
            #pragma unroll
            for (int nt = 0; nt < 8; ++nt)
                #pragma unroll
                for (int q = 0; q < 4; ++q) acc[fr][nt][q] = 0.f;

        auto build_A = [&](int cc) {
            const int f = cc >> lg2;
            const int g0 = ((cc & ((1 << lg2) - 1)) << 4) + c0;
            #pragma unroll
            for (int fr = 0; fr < 2; ++fr) {
                #pragma unroll
                for (int j2 = 0; j2 < 2; ++j2) {
                    const int row = wm * 32 + r0 + fr * 16 + j2 * 8;
                    const float x = x0t[row * 36 + f];
                    const float2 p0 = *(const float2*)(st + row * 132 + g0);
                    const float2 p1 = *(const float2*)(st + row * 132 + g0 + 8);
                    float z00 = x * p0.x, z01 = x * p0.y;
                    float z10 = x * p1.x, z11 = x * p1.y;
                    uint32_t h0 = pkbf(z00, z01), h1 = pkbf(z10, z11);
                    al[fr][j2]     = pkbf(z00 - bflo(h0), z01 - bfhi(h0));
                    al[fr][2 + j2] = pkbf(z10 - bflo(h1), z11 - bfhi(h1));
                    ah[fr][j2]     = h0;
                    ah[fr][2 + j2] = h1;
                }
            }
        };

        auto burst48 = [&]() {
            #pragma unroll
            for (int j = 0; j < 4; ++j) {
                mma16816(acc[0][2 * j],     ah[0], bh[j][0], bh[j][1]);
                mma16816(acc[1][2 * j],     ah[1], bh[j][0], bh[j][1]);
                mma16816(acc[0][2 * j + 1], ah[0], bh[j][2], bh[j][3]);
                mma16816(acc[1][2 * j + 1], ah[1], bh[j][2], bh[j][3]);
                mma16816(acc[0][2 * j],     al[0], bh[j][0], bh[j][1]);
                mma16816(acc[1][2 * j],     al[1], bh[j][0], bh[j][1]);
                mma16816(acc[0][2 * j + 1], al[0], bh[j][2], bh[j][3]);
                mma16816(acc[1][2 * j + 1], al[1], bh[j][2], bh[j][3]);
                mma16816(acc[0][2 * j],     ah[0], bl[j][0], bl[j][1]);
                mma16816(acc[1][2 * j],     ah[1], bl[j][0], bl[j][1]);
                mma16816(acc[0][2 * j + 1], ah[0], bl[j][2], bl[j][3]);
                mma16816(acc[1][2 * j + 1], ah[1], bl[j][2], bl[j][3]);
            }
        };

        auto ldsmB = [&](uint32_t stb) {
            #pragma unroll
            for (int j = 0; j < 4; ++j)
                ldsm4(stb + nroff[j], bh[j][0], bh[j][1], bh[j][2], bh[j][3]);
            #pragma unroll
            for (int j = 0; j < 4; ++j)
                ldsm4(stb + WTERM + nroff[j], bl[j][0], bl[j][1], bl[j][2], bl[j][3]);
        };

        build_A(0);   // state is synced at this point

        #pragma unroll 1
        for (int cc = 0; cc < nchunk; cc += 2) {
            const uint32_t stg0 = wsm + (uint32_t)(cg % NSTAGE) * CHUNK_BYTES;
            const uint32_t stg1 = wsm + (uint32_t)((cg + 1) % NSTAGE) * CHUNK_BYTES;
            const uint32_t stg2 = wsm + (uint32_t)((cg + 2) % NSTAGE) * CHUNK_BYTES;

            // B for chunk cg — stage data rigorously landed (wait0+barrier)
            ldsmB(stg0);

            // cp.async chunk cg+2 -> stage (cg+2)%3  (its last readers were
            // pre-previous-barrier: chunk cg-1 mid-iteration ldsm)
            if (cg + 2 < KCH) {
                const unsigned char* src = WT_buf + (size_t)(cg + 2) * CHUNK_BYTES + tid * 16;
                cpasync16(stg2 + tid * 16,        src);
                cpasync16(stg2 + tid * 16 + 4096, src + 4096);
            }

            // ---- burst 1 (chunk cg) ----
            burst48();

            // A and B for chunk cg+1
            build_A(cc + 1);
            ldsmB(stg1);

            // cp.async chunk cg+3 -> stage cg%3 (chunk cg's B already consumed
            // into registers; issued well after all warps' top-of-iter ldsm)
            if (cg + 3 < KCH) {
                const unsigned char* src = WT_buf + (size_t)(cg + 3) * CHUNK_BYTES + tid * 16;
                cpasync16(stg0 + tid * 16,        src);
                cpasync16(stg0 + tid * 16 + 4096, src + 4096);
            }
            CP_COMMIT();   // one group per iteration (cg+2, cg+3)

            // ---- burst 2 (chunk cg+1) ----
            burst48();

            // A for first chunk of next iteration (same layer only)
            if (cc + 2 < nchunk) build_A(cc + 2);

            CP_WAIT0();        // own group done (issued ~1 iter ago: no stall)
            __syncthreads();   // CTA-wide: stages for cg+2/cg+3 fully landed;
                               // WAR fence for this iteration's ldsm readers
            cg += 2;
        }

        // ---- epilogue: output reduction (sum over d) + state update ----
        const int bgl = b0g + wm;
        #pragma unroll
        for (int nt = 0; nt < 8; ++nt) {
            float s0 = acc[0][nt][0] + acc[0][nt][2] + acc[1][nt][0] + acc[1][nt][2];
            float s1 = acc[0][nt][1] + acc[0][nt][3] + acc[1][nt][1] + acc[1][nt][3];
            #pragma unroll
            for (int off = 4; off <= 16; off <<= 1) {
                s0 += __shfl_xor_sync(0xffffffffu, s0, off);
                s1 += __shfl_xor_sync(0xffffffffu, s1, off);
            }
            if (lane < 4) {
                const int col = wn * 64 + nt * 8 + c0;
                float2 o;
                o.x = s0 + 32.0f * bias[l * 128 + col];
                o.y = s1 + 32.0f * bias[l * 128 + col + 1];
                *(float2*)(out + (size_t)bgl * 384 + l * 128 + col) = o;
            }
        }

        if (l < 2) {
            // state[row][h] = C[row][h] + bias_l[h]
            #pragma unroll
            for (int fr = 0; fr < 2; ++fr) {
                #pragma unroll
                for (int nt = 0; nt < 8; ++nt) {
                    const int col = wn * 64 + nt * 8 + c0;
                    const float bx = bias[l * 128 + col];
                    const float by = bias[l * 128 + col + 1];
                    const int rowa = wm * 32 + r0 + fr * 16;
                    float2 v0, v1;
                    v0.x = acc[fr][nt][0] + bx; v0.y = acc[fr][nt][1] + by;
                    v1.x = acc[fr][nt][2] + bx; v1.y = acc[fr][nt][3] + by;
                    *(float2*)(st + rowa * 132 + col)       = v0;
                    *(float2*)(st + (rowa + 8) * 132 + col) = v1;
                }
            }
            __syncthreads();   // state visible before next layer's A builds
        }
    }
}

extern "C" void kernel_launch(void* const* d_in, const int* in_sizes, int n_in,
                              void* d_out, int out_size) {
    const float* X  = (const float*)d_in[0];
    const float* W0 = (const float*)d_in[1];
    const float* W1 = (const float*)d_in[2];
    const float* W2 = (const float*)d_in[3];
    const float* B0 = (const float*)d_in[4];
    const float* B1 = (const float*)d_in[5];
    const float* B2 = (const float*)d_in[6];
    float* out = (float*)d_out;

    const int B = in_sizes[0] / 1024;

    cudaFuncSetAttribute(cin_hmma_kernel,
                         cudaFuncAttributeMaxDynamicSharedMemorySize, SMEM_TOTAL);

    prep_w<<<(9216 * 128 + 255) / 256, 256>>>(W0, W1, W2);
    cin_hmma_kernel<<<B / 4, NT, SMEM_TOTAL>>>(X, B0, B1, B2, out);
}

// round 11
// speedup vs baseline: 1.0173x; 1.0173x over previous
#include <cuda_runtime.h>
#include <cuda_bf16.h>
#include <cstdint>

// CIN (xDeepFM) fused 3-layer kernel via mma.sync (HMMA) bf16 3-term split.
// Round 10: R9 mbarrier dataflow (3-stage W ring, zero per-chunk CTA barriers)
// with the layer-boundary race fixed: __syncthreads() after each layer's
// k-loop before the state (st) update, and consumer empty-arrive moved after
// the MMA burst. Chunk p produced by warp (p&7) during its iteration p-3.

#define NT 256
#define KCH 576                 // total 16-wide k chunks: 64 + 256 + 256
#define WTERM 4096              // 128 n-rows * 32B (16 bf16), swizzled
#define CHUNK_BYTES (2 * WTERM) // 8192: hi term + lo term
#define NSTAGE 3

// smem byte offsets
#define SM_X0T   0                  // 128 rows * 36 f32 = 18432
#define SM_ST    18432              // 128 rows * 132 f32 = 67584
#define SM_W     86016              // 3 stages * 8192 = 24576
#define SM_BIAS  110592             // 384 f32 = 1536
#define SM_MBAR  112128             // 6 mbarriers * 8B
#define SMEM_TOTAL 112192

__device__ __align__(16) unsigned char WT_buf[(size_t)KCH * CHUNK_BYTES]; // 4.7MB

// ------------- helpers -------------
__device__ __forceinline__ uint32_t smem_u32(const void* p) {
    uint32_t a;
    asm("{ .reg .u64 t; cvta.to.shared.u64 t, %1; cvt.u32.u64 %0, t; }" : "=r"(a) : "l"(p));
    return a;
}
__device__ __forceinline__ uint32_t pkbf(float lo, float hi) {
    uint32_t r;  // first asm operand -> high half
    asm("cvt.rn.bf16x2.f32 %0, %1, %2;" : "=r"(r) : "f"(hi), "f"(lo));
    return r;
}
__device__ __forceinline__ float bflo(uint32_t p) { return __uint_as_float(p << 16); }
__device__ __forceinline__ float bfhi(uint32_t p) { return __uint_as_float(p & 0xffff0000u); }

__device__ __forceinline__ void ldsm4(uint32_t a, uint32_t& r0, uint32_t& r1,
                                      uint32_t& r2, uint32_t& r3) {
    asm volatile("ldmatrix.sync.aligned.m8n8.x4.shared.b16 {%0,%1,%2,%3}, [%4];"
                 : "=r"(r0), "=r"(r1), "=r"(r2), "=r"(r3) : "r"(a));
}
__device__ __forceinline__ void mma16816(float* c, const uint32_t* a, uint32_t b0, uint32_t b1) {
    asm volatile("mma.sync.aligned.m16n8k16.row.col.f32.bf16.bf16.f32 "
                 "{%0,%1,%2,%3}, {%4,%5,%6,%7}, {%8,%9}, {%0,%1,%2,%3};"
                 : "+f"(c[0]), "+f"(c[1]), "+f"(c[2]), "+f"(c[3])
                 : "r"(a[0]), "r"(a[1]), "r"(a[2]), "r"(a[3]), "r"(b0), "r"(b1));
}
__device__ __forceinline__ void cpasync16(uint32_t dst, const void* src) {
    asm volatile("cp.async.cg.shared.global [%0], [%1], 16;" :: "r"(dst), "l"(src) : "memory");
}
__device__ __forceinline__ void cp_mbar_arrive_noinc(uint32_t a) {
    asm volatile("cp.async.mbarrier.arrive.noinc.shared.b64 [%0];" :: "r"(a) : "memory");
}
__device__ __forceinline__ void mbar_init(uint32_t a, uint32_t c) {
    asm volatile("mbarrier.init.shared.b64 [%0], %1;" :: "r"(a), "r"(c) : "memory");
}
__device__ __forceinline__ void mbar_arrive(uint32_t a) {
    asm volatile("mbarrier.arrive.shared.b64 _, [%0];" :: "r"(a) : "memory");
}
__device__ __forceinline__ void mbar_wait(uint32_t a, uint32_t parity) {
    uint32_t done;
    asm volatile("{\n\t.reg .pred p;\n\t"
        "mbarrier.try_wait.parity.acquire.cta.shared::cta.b64 p, [%1], %2, 0x989680;\n\t"
        "selp.b32 %0, 1, 0, p;\n\t}"
        : "=r"(done) : "r"(a), "r"(parity) : "memory");
    while (!done) {
        asm volatile("{\n\t.reg .pred p;\n\t"
            "mbarrier.try_wait.parity.acquire.cta.shared::cta.b64 p, [%1], %2, 0x989680;\n\t"
            "selp.b32 %0, 1, 0, p;\n\t}"
            : "=r"(done) : "r"(a), "r"(parity) : "memory");
    }
}

// swizzled byte offset of the 16B half (n-row, khalf) within one term
__device__ __host__ __forceinline__ int wsw(int n, int khalf) {
    return n * 32 + ((khalf ^ ((n >> 2) & 1)) << 4);
}

// ------------- prep: split W -> bf16 hi/lo, swizzled chunk layout == smem -------------
__global__ void prep_w(const float* __restrict__ W0, const float* __restrict__ W1,
                       const float* __restrict__ W2) {
    int i = blockIdx.x * blockDim.x + threadIdx.x;   // over 9216*128
    if (i >= 9216 * 128) return;
    int k = i >> 7, n = i & 127;
    float w;
    if (k < 1024)      w = W0[k * 128 + n];
    else if (k < 5120) w = W1[(k - 1024) * 128 + n];
    else               w = W2[(k - 5120) * 128 + n];
    __nv_bfloat16 hb = __float2bfloat16(w);
    __nv_bfloat16 lb = __float2bfloat16(w - __bfloat162float(hb));
    int c = k >> 4, kk = k & 15;
    int off = wsw(n, kk >> 3) + (kk & 7) * 2;
    unsigned char* base = WT_buf + (size_t)c * CHUNK_BYTES + off;
    *(__nv_bfloat16*)(base)         = hb;   // hi term
    *(__nv_bfloat16*)(base + WTERM) = lb;   // lo term
}

// ------------- main kernel -------------
__global__ void __launch_bounds__(NT, 2)
cin_hmma_kernel(const float* __restrict__ X,
                const float* __restrict__ B0, const float* __restrict__ B1,
                const float* __restrict__ B2, float* __restrict__ out)
{
    extern __shared__ __align__(16) char smem[];
    float* x0t  = (float*)(smem + SM_X0T);   // [row][36] (f stride)
    float* st   = (float*)(smem + SM_ST);    // [row][132] (g stride)
    float* bias = (float*)(smem + SM_BIAS);  // [384]
    const uint32_t sb  = smem_u32(smem);
    const uint32_t wsm = sb + SM_W;
    const uint32_t mb  = sb + SM_MBAR;
    #define MB_FULL(s)  (mb + (uint32_t)(s) * 8)
    #define MB_EMPTY(s) (mb + 24 + (uint32_t)(s) * 8)

    const int tid = threadIdx.x, wid = tid >> 5, lane = tid & 31;
    const int wm = wid >> 1, wn = wid & 1;     // warp grid 4(m=batch) x 2(n)
    const int b0g = blockIdx.x * 4;
    const int r0 = lane >> 2;                  // row-in-frag 0..7
    const int c0 = (lane & 3) * 2;             // col pair base

    // ---- mbarrier init ----
    if (tid == 0) {
        #pragma unroll
        for (int s = 0; s < NSTAGE; ++s) {
            mbar_init(MB_FULL(s), 32);   // 32 producer-lane cp completions
            mbar_init(MB_EMPTY(s), 8);   // 8 consumer-warp arrivals
        }
    }
    __syncthreads();

    // ---- prologue: warps 0..2 produce chunks 0..2 ----
    if (wid < NSTAGE) {
        const unsigned char* src = WT_buf + (size_t)wid * CHUNK_BYTES + lane * 16;
        const uint32_t dst = wsm + (uint32_t)wid * CHUNK_BYTES + lane * 16;
        #pragma unroll
        for (int u = 0; u < 16; ++u) cpasync16(dst + u * 512, src + u * 512);
        cp_mbar_arrive_noinc(MB_FULL(wid));
    }

    // ---- load x0 transposed + init state + bias ----
    {
        const float* Xb = X + (size_t)b0g * 1024;
        for (int i = tid; i < 4096; i += NT) {
            int b = i >> 10, f = (i >> 5) & 31, d = i & 31;
            float v = Xb[i];
            int row = b * 32 + d;
            x0t[row * 36 + f] = v;
            st[row * 132 + f] = v;     // layer-0 state = x0 (g = f)
        }
        for (int i = tid; i < 128; i += NT) {
            bias[i] = B0[i]; bias[128 + i] = B1[i]; bias[256 + i] = B2[i];
        }
    }
    __syncthreads();   // x0t/st/bias visible

    // per-j ldsm swizzled offsets within a term
    const int kh = (lane >> 3) & 1;
    uint32_t nroff[4];
    #pragma unroll
    for (int j = 0; j < 4; ++j) {
        const int nrow = (wn * 8 + 2 * j + ((lane >> 4) & 1)) * 8 + (lane & 7);
        nroff[j] = (uint32_t)wsw(nrow, kh);
    }

    uint32_t bh[4][4], bl[4][4];    // B fragments
    uint32_t ah[2][4], al[2][4];    // A fragments

    int cg = 0;      // global chunk counter
    int cs = 0;      // consumer full-wait cursor: stage
    int cphF = 0;    // consumer full-wait cursor: phase parity

    #pragma unroll 1
    for (int l = 0; l < 3; ++l) {
        const int lg2 = (l == 0) ? 1 : 3;        // chunks per f = fk/16
        const int nchunk = (l == 0) ? 64 : 256;

        float acc[2][8][4];
        #pragma unroll
        for (int fr = 0; fr < 2; ++fr)
            #pragma unroll
            for (int nt = 0; nt < 8; ++nt)
                #pragma unroll
                for (int q = 0; q < 4; ++q) acc[fr][nt][q] = 0.f;

        auto build_A = [&](int cc) {
            const int f = cc >> lg2;
            const int g0 = ((cc & ((1 << lg2) - 1)) << 4) + c0;
            #pragma unroll
            for (int fr = 0; fr < 2; ++fr) {
                #pragma unroll
                for (int j2 = 0; j2 < 2; ++j2) {
                    const int row = wm * 32 + r0 + fr * 16 + j2 * 8;
                    const float x = x0t[row * 36 + f];
                    const float2 p0 = *(const float2*)(st + row * 132 + g0);
                    const float2 p1 = *(const float2*)(st + row * 132 + g0 + 8);
                    float z00 = x * p0.x, z01 = x * p0.y;
                    float z10 = x * p1.x, z11 = x * p1.y;
                    uint32_t h0 = pkbf(z00, z01), h1 = pkbf(z10, z11);
                    al[fr][j2]     = pkbf(z00 - bflo(h0), z01 - bfhi(h0));
                    al[fr][2 + j2] = pkbf(z10 - bflo(h1), z11 - bfhi(h1));
                    ah[fr][j2]     = h0;
                    ah[fr][2 + j2] = h1;
                }
            }
        };

        build_A(0);   // state is synced at this point

        #pragma unroll 1
        for (int cc = 0; cc < nchunk; ++cc) {
            // ---- acquire current chunk's W stage ----
            mbar_wait(MB_FULL(cs), (uint32_t)cphF);
            const uint32_t stg = wsm + (uint32_t)cs * CHUNK_BYTES;
            #pragma unroll
            for (int j = 0; j < 4; ++j)
                ldsm4(stg + nroff[j], bh[j][0], bh[j][1], bh[j][2], bh[j][3]);
            #pragma unroll
            for (int j = 0; j < 4; ++j)
                ldsm4(stg + WTERM + nroff[j], bl[j][0], bl[j][1], bl[j][2], bl[j][3]);
            const int cs_used = cs;
            cs = (cs == NSTAGE - 1) ? 0 : cs + 1;
            if (cs == 0) cphF ^= 1;

            // ---- 48-MMA burst for chunk cg ----
            #pragma unroll
            for (int j = 0; j < 4; ++j) {
                mma16816(acc[0][2 * j],     ah[0], bh[j][0], bh[j][1]);
                mma16816(acc[1][2 * j],     ah[1], bh[j][0], bh[j][1]);
                mma16816(acc[0][2 * j + 1], ah[0], bh[j][2], bh[j][3]);
                mma16816(acc[1][2 * j + 1], ah[1], bh[j][2], bh[j][3]);
                mma16816(acc[0][2 * j],     al[0], bh[j][0], bh[j][1]);
                mma16816(acc[1][2 * j],     al[1], bh[j][0], bh[j][1]);
                mma16816(acc[0][2 * j + 1], al[0], bh[j][2], bh[j][3]);
                mma16816(acc[1][2 * j + 1], al[1], bh[j][2], bh[j][3]);
                mma16816(acc[0][2 * j],     ah[0], bl[j][0], bl[j][1]);
                mma16816(acc[1][2 * j],     ah[1], bl[j][0], bl[j][1]);
                mma16816(acc[0][2 * j + 1], ah[0], bl[j][2], bl[j][3]);
                mma16816(acc[1][2 * j + 1], ah[1], bl[j][2], bl[j][3]);
            }

            // ---- release the stage only after the burst (B safely consumed
            //      from registers; removes any ldsm-vs-cp.async WAR doubt) ----
            if (lane == 0) mbar_arrive(MB_EMPTY(cs_used));

            // ---- rotating producer: this warp fills chunk cg+3 (stage of cg)
            //      while its own 48 MMAs drain through the tensor pipe ----
            {
                const int p = cg + 3;
                if (p < KCH && (p & 7) == wid) {
                    const int m = p / 3;                 // stage reuse index (>=1)
                    const int ps = p - m * 3;            // p % 3
                    mbar_wait(MB_EMPTY(ps), (uint32_t)((m - 1) & 1));
                    const unsigned char* src = WT_buf + (size_t)p * CHUNK_BYTES + lane * 16;
                    const uint32_t dst = wsm + (uint32_t)ps * CHUNK_BYTES + lane * 16;
                    #pragma unroll
                    for (int u = 0; u < 16; ++u) cpasync16(dst + u * 512, src + u * 512);
                    cp_mbar_arrive_noinc(MB_FULL(ps));
                }
            }

            // ---- A for next chunk of this layer ----
            if (cc + 1 < nchunk) build_A(cc + 1);

            ++cg;
        }

        // ---- CRITICAL: all warps' build_A reads of st for this layer are
        //      done before anyone overwrites st (warps share st ROWS across
        //      the wn split). This is the barrier whose absence broke R9. ----
        __syncthreads();

        // ---- epilogue: output reduction (sum over d) + state update ----
        const int bgl = b0g + wm;
        #pragma unroll
        for (int nt = 0; nt < 8; ++nt) {
            float s0 = acc[0][nt][0] + acc[0][nt][2] + acc[1][nt][0] + acc[1][nt][2];
            float s1 = acc[0][nt][1] + acc[0][nt][3] + acc[1][nt][1] + acc[1][nt][3];
            #pragma unroll
            for (int off = 4; off <= 16; off <<= 1) {
                s0 += __shfl_xor_sync(0xffffffffu, s0, off);
                s1 += __shfl_xor_sync(0xffffffffu, s1, off);
            }
            if (lane < 4) {
                const int col = wn * 64 + nt * 8 + c0;
                float2 o;
                o.x = s0 + 32.0f * bias[l * 128 + col];
                o.y = s1 + 32.0f * bias[l * 128 + col + 1];
                *(float2*)(out + (size_t)bgl * 384 + l * 128 + col) = o;
            }
        }

        if (l < 2) {
            // state[row][h] = C[row][h] + bias_l[h]
            #pragma unroll
            for (int fr = 0; fr < 2; ++fr) {
                #pragma unroll
                for (int nt = 0; nt < 8; ++nt) {
                    const int col = wn * 64 + nt * 8 + c0;
                    const float bx = bias[l * 128 + col];
                    const float by = bias[l * 128 + col + 1];
                    const int rowa = wm * 32 + r0 + fr * 16;
                    float2 v0, v1;
                    v0.x = acc[fr][nt][0] + bx; v0.y = acc[fr][nt][1] + by;
                    v1.x = acc[fr][nt][2] + bx; v1.y = acc[fr][nt][3] + by;
                    *(float2*)(st + rowa * 132 + col)       = v0;
                    *(float2*)(st + (rowa + 8) * 132 + col) = v1;
                }
            }
            __syncthreads();   // state visible before next layer's A builds
        }
    }
}

extern "C" void kernel_launch(void* const* d_in, const int* in_sizes, int n_in,
                              void* d_out, int out_size) {
    const float* X  = (const float*)d_in[0];
    const float* W0 = (const float*)d_in[1];
    const float* W1 = (const float*)d_in[2];
    const float* W2 = (const float*)d_in[3];
    const float* B0 = (const float*)d_in[4];
    const float* B1 = (const float*)d_in[5];
    const float* B2 = (const float*)d_in[6];
    float* out = (float*)d_out;

    const int B = in_sizes[0] / 1024;

    cudaFuncSetAttribute(cin_hmma_kernel,
                         cudaFuncAttributeMaxDynamicSharedMemorySize, SMEM_TOTAL);

    prep_w<<<(9216 * 128 + 255) / 256, 256>>>(W0, W1, W2);
    cin_hmma_kernel<<<B / 4, NT, SMEM_TOTAL>>>(X, B0, B1, B2, out);
}